// round 13
// baseline (speedup 1.0000x reference)
#include <cuda_runtime.h>
#include <cuda_bf16.h>

#define G_SIZE 4096
#define B_SIZE 16
#define NCH 15
#define D_MAX 20          // Taylor degree: terms d = 0..20
#define ND (D_MAX + 1)    // 21
#define NDG (ND / 3)      // 7 degree-groups of 3
#define NSPL 4
#define LPER (G_SIZE / NSPL)   // 1024

// Split-innermost layout: Mo_part[((c*ND + d)*B_SIZE + b)*NSPL + sp]
__device__ float Mo_part[NCH * ND * B_SIZE * NSPL];

#define LOG2E 1.4426950408889634f

__device__ __forceinline__ float ex2f(float x) {
    float r; asm("ex2.approx.ftz.f32 %0, %1;" : "=f"(r) : "f"(x)); return r;
}

// gl^e by binary exponentiation (e uniform across CTA -> no divergence)
__device__ __forceinline__ float powu(float g, int e) {
    float p = 1.0f, b = g;
#pragma unroll
    for (int k = 0; k < 5; ++k) {            // e <= 20 < 32
        if (e & 1) p *= b;
        b *= b;
        e >>= 1;
    }
    return p;
}

// Moments partials: 512 threads = 16 warps, ONE b per warp (b = wid).
// grid = (7 degree-groups, 15 channels, 4 l-splits).
__global__ __launch_bounds__(512) void moments_kernel(const float* __restrict__ xi,
                                                      const float* __restrict__ grid,
                                                      const float* __restrict__ gw,
                                                      const float* __restrict__ density) {
    __shared__ __align__(16) float prod[3][LPER];      // 12 KB
    const int dg = blockIdx.x;      // 0..6 -> degrees 3dg..3dg+2
    const int c  = blockIdx.y;
    const int sp = blockIdx.z;      // 0..3
    const int tid = threadIdx.x;
    const int l0 = sp * LPER;

    const float xi_t = 1.0f + ex2f(-xi[c] * LOG2E);
    const float cg = -xi_t * LOG2E;
    const int e0 = 3 * dg;

    // Stage: threads 0..255 each build 4 l-entries for all 3 degree rows
    if (tid < 256) {
        float4 g4 = ((const float4*)(grid + l0))[tid];
        float4 w4 = ((const float4*)(gw + l0))[tid];
        float4 r0, r1, r2;
        {
            float g = g4.x, F = w4.x * ex2f(g * g * cg), p = powu(g, e0);
            r0.x = F * p; p *= g; r1.x = F * p; p *= g; r2.x = F * p;
        }
        {
            float g = g4.y, F = w4.y * ex2f(g * g * cg), p = powu(g, e0);
            r0.y = F * p; p *= g; r1.y = F * p; p *= g; r2.y = F * p;
        }
        {
            float g = g4.z, F = w4.z * ex2f(g * g * cg), p = powu(g, e0);
            r0.z = F * p; p *= g; r1.z = F * p; p *= g; r2.z = F * p;
        }
        {
            float g = g4.w, F = w4.w * ex2f(g * g * cg), p = powu(g, e0);
            r0.w = F * p; p *= g; r1.w = F * p; p *= g; r2.w = F * p;
        }
        ((float4*)prod[0])[tid] = r0;
        ((float4*)prod[1])[tid] = r1;
        ((float4*)prod[2])[tid] = r2;
    }
    __syncthreads();

    const int wid = tid >> 5, lane = tid & 31;
    const int b = wid;                         // one batch per warp

    float t = 2.0f * xi_t;
    float coef0 = 1.0f;
    for (int i = 1; i <= e0; ++i) coef0 = coef0 * t / (float)i;
    float coef1 = coef0 * t / (float)(e0 + 1);
    float coef2 = coef1 * t / (float)(e0 + 2);

    const float4* p0 = (const float4*)prod[0];
    const float4* p1 = (const float4*)prod[1];
    const float4* p2 = (const float4*)prod[2];
    const float4* dr = (const float4*)(density + b * G_SIZE + l0);

    float s0 = 0.f, s1 = 0.f, s2 = 0.f;
    float u0 = 0.f, u1 = 0.f, u2 = 0.f;
#pragma unroll
    for (int i = 0; i < LPER / 4 / 32; ++i) {      // 8 iters, fully unrolled
        int ix = lane + i * 32;
        float4 d4 = dr[ix];
        float4 a0 = p0[ix], a1 = p1[ix], a2 = p2[ix];
        s0 += d4.x * a0.x + d4.y * a0.y;
        u0 += d4.z * a0.z + d4.w * a0.w;
        s1 += d4.x * a1.x + d4.y * a1.y;
        u1 += d4.z * a1.z + d4.w * a1.w;
        s2 += d4.x * a2.x + d4.y * a2.y;
        u2 += d4.z * a2.z + d4.w * a2.w;
    }
    s0 += u0; s1 += u1; s2 += u2;
#pragma unroll
    for (int o = 16; o; o >>= 1) {
        s0 += __shfl_xor_sync(0xffffffffu, s0, o);
        s1 += __shfl_xor_sync(0xffffffffu, s1, o);
        s2 += __shfl_xor_sync(0xffffffffu, s2, o);
    }
    if (lane == 0) {
        Mo_part[((c * ND + e0 + 0) * B_SIZE + b) * NSPL + sp] = s0 * coef0;
        Mo_part[((c * ND + e0 + 1) * B_SIZE + b) * NSPL + sp] = s1 * coef1;
        Mo_part[((c * ND + e0 + 2) * B_SIZE + b) * NSPL + sp] = s2 * coef2;
    }
}

// Output: 512 threads = 4 batch-groups x 128 m-lanes, each thread owns 2 m's.
// grid = (16 m-blocks of 256, 16 channels). Per Horner step: 1 LDS.128 -> 8 FMAs.
__global__ __launch_bounds__(512) void output_kernel(const float* __restrict__ xi,
                                                     const float* __restrict__ grid,
                                                     const float* __restrict__ density,
                                                     float* __restrict__ out) {
    const int c = blockIdx.y;
    const int tid = threadIdx.x;
    const int bg = tid >> 7;          // 0..3 -> batches 4*bg..4*bg+3
    const int m0 = blockIdx.x * 256 + (tid & 127);
    const int m1 = m0 + 128;

    if (c == NCH) {   // raw density channel
#pragma unroll
        for (int q = 0; q < 4; ++q) {
            int b = 4 * bg + q;
            out[(b * 16 + NCH) * G_SIZE + m0] = density[b * G_SIZE + m0];
            out[(b * 16 + NCH) * G_SIZE + m1] = density[b * G_SIZE + m1];
        }
        return;
    }

    __shared__ __align__(16) float sMo[ND * B_SIZE];   // 336 floats
    if (tid < ND * B_SIZE) {
        float4 v = ((const float4*)Mo_part)[c * ND * B_SIZE + tid];
        sMo[tid] = (v.x + v.y) + (v.z + v.w);
    }
    __syncthreads();

    float gm0 = grid[m0], gm1 = grid[m1];
    float xi_t = 1.0f + ex2f(-xi[c] * LOG2E);
    float half_xi = 0.5f * xi_t;
    float scale0 = half_xi * ex2f(-gm0 * gm0 * xi_t * LOG2E);
    float scale1 = half_xi * ex2f(-gm1 * gm1 * xi_t * LOG2E);

    // 8 independent Horner chains; one broadcast LDS.128 per degree step feeds 8 FMAs.
    const float4* col = (const float4*)(sMo) + bg;     // row d -> col[d*4]
    float4 w = col[D_MAX * 4];
    float a0 = w.x, a1 = w.y, a2 = w.z, a3 = w.w;
    float b0 = w.x, b1 = w.y, b2 = w.z, b3 = w.w;
#pragma unroll
    for (int d = D_MAX - 1; d >= 0; --d) {
        float4 v = col[d * 4];
        a0 = a0 * gm0 + v.x;
        a1 = a1 * gm0 + v.y;
        a2 = a2 * gm0 + v.z;
        a3 = a3 * gm0 + v.w;
        b0 = b0 * gm1 + v.x;
        b1 = b1 * gm1 + v.y;
        b2 = b2 * gm1 + v.z;
        b3 = b3 * gm1 + v.w;
    }

    const int bb = 4 * bg;
    out[((bb + 0) * 16 + c) * G_SIZE + m0] = a0 * scale0;
    out[((bb + 1) * 16 + c) * G_SIZE + m0] = a1 * scale0;
    out[((bb + 2) * 16 + c) * G_SIZE + m0] = a2 * scale0;
    out[((bb + 3) * 16 + c) * G_SIZE + m0] = a3 * scale0;
    out[((bb + 0) * 16 + c) * G_SIZE + m1] = b0 * scale1;
    out[((bb + 1) * 16 + c) * G_SIZE + m1] = b1 * scale1;
    out[((bb + 2) * 16 + c) * G_SIZE + m1] = b2 * scale1;
    out[((bb + 3) * 16 + c) * G_SIZE + m1] = b3 * scale1;
}

extern "C" void kernel_launch(void* const* d_in, const int* in_sizes, int n_in,
                              void* d_out, int out_size) {
    const float* density = (const float*)d_in[0];  // (16,1,4096)
    const float* xi      = (const float*)d_in[1];  // (15,)
    const float* grid    = (const float*)d_in[2];  // (4096,)
    const float* gw      = (const float*)d_in[3];  // (4096,)
    float* out = (float*)d_out;                    // (16,16,4096)

    moments_kernel<<<dim3(NDG, NCH, NSPL), 512>>>(xi, grid, gw, density);
    output_kernel<<<dim3(G_SIZE / 256, NCH + 1), 512>>>(xi, grid, density, out);
}